// round 9
// baseline (speedup 1.0000x reference)
#include <cuda_runtime.h>
#include <cuda_bf16.h>

#define T_MAX 11

// Inter-block communication scratch (zero-init; reset at end of each launch).
__device__ float g_e[1024];
__device__ float g_w[1024];
__device__ int   g_off[1024];
__device__ int   g_cnt[1024];
__device__ unsigned int g_ctr  = 0;   // prep-blocks-finished counter
__device__ unsigned int g_flag = 0;   // weights-ready flag
__device__ unsigned int g_done = 0;   // blocks-finished counter (for reset)

// ---------------------------------------------------------------------------
// Single launch. Grid (GX, S) where GX = n4_bert/256 + 1.  256 threads.
//  - blocks with linear bid < rows: compute exp(dot(hist[bid],W)+b) -> g_e.
//    Last of them (atomic elect) computes softmax/offsets/probs, sets g_flag.
//  - ALL blocks spin on g_flag, then run the proven streaming segment-sum:
//      x <  GX-1 : 256 float4 chunk of new_bert for segment blockIdx.y
//      x == GX-1 : new_mtl row for segment blockIdx.y
//  - last block to exit resets flag/counters (graph-replay idempotent).
// ---------------------------------------------------------------------------
__global__ void __launch_bounds__(256, 8)
k_all(const float* __restrict__ bert,
      const float* __restrict__ hist,
      const float* __restrict__ mtl,
      const float* __restrict__ Wv,
      const float* __restrict__ bv,
      const int*   __restrict__ slice_mask,
      float* __restrict__ out_bert,
      float* __restrict__ out_mtl,
      float* __restrict__ out_probs,
      int rows, int hidden, int n4_bert, int n4_mtl, int S)
{
    const int tid  = threadIdx.x;
    const int lane = tid & 31;
    const int warp = tid >> 5;
    const int s    = blockIdx.y;
    const unsigned int bid   = blockIdx.x + gridDim.x * blockIdx.y;
    const unsigned int total = gridDim.x * gridDim.y;

    __shared__ float s_red[8];
    __shared__ int   s_fin;

    // ================= prep role: one row-dot per block =================
    if (bid < (unsigned)rows) {
        const int r = bid;
        const int nv4 = hidden >> 2;
        const float4* hr = (const float4*)(hist + (size_t)r * hidden);
        const float4* wv = (const float4*)Wv;
        float acc = 0.f;
        for (int c = tid; c < nv4; c += 256) {   // 1 parallel round @768
            float4 h = __ldg(hr + c);
            float4 w = __ldg(wv + c);
            acc = fmaf(h.x, w.x, acc);
            acc = fmaf(h.y, w.y, acc);
            acc = fmaf(h.z, w.z, acc);
            acc = fmaf(h.w, w.w, acc);
        }
        #pragma unroll
        for (int o = 16; o; o >>= 1)
            acc += __shfl_down_sync(0xffffffffu, acc, o);
        if (lane == 0) s_red[warp] = acc;
        __syncthreads();
        if (tid == 0) {
            float logit = bv[0];
            #pragma unroll
            for (int k = 0; k < 8; k++) logit += s_red[k];
            g_e[r] = __expf(logit);
            __threadfence();
            unsigned int old = atomicAdd(&g_ctr, 1u);
            s_fin = (old == (unsigned)rows - 1) ? 1 : 0;
        }
        __syncthreads();

        if (s_fin) {
            // -------- finisher: softmax weights + probs output --------
            __shared__ int   sh_cnt[64], sh_off[64];
            __shared__ float sh_e[256];
            if (tid < S) sh_cnt[tid] = slice_mask[tid];
            __syncthreads();
            if (tid == 0) {
                int off = 0;
                for (int t = 0; t < S; t++) { sh_off[t] = off; off += sh_cnt[t]; }
            }
            __syncthreads();
            if (tid < rows) sh_e[tid] = ((volatile float*)g_e)[tid];
            for (int i = tid; i < S * T_MAX; i += 256)  // d_out poisoned
                out_probs[i] = 0.f;
            __syncthreads();
            if (tid < S) {
                const int off = sh_off[tid], cnt = sh_cnt[tid];
                g_off[tid] = off;
                g_cnt[tid] = cnt;
                float sum = 0.f;
                for (int j = 0; j < cnt; j++) sum += sh_e[off + j];
                const float inv  = 1.f / sum;
                const int   padl = T_MAX - cnt;
                for (int j = 0; j < cnt; j++) {
                    float w = sh_e[off + j] * inv;
                    g_w[off + j] = w;
                    out_probs[tid * T_MAX + padl + j] = w;
                }
            }
            __threadfence();
            __syncthreads();
            if (tid == 0) atomicExch(&g_flag, 1u);
        }
    }

    // ================= wait for weights =================
    if (tid == 0) {
        volatile unsigned int* f = &g_flag;
        while (*f == 0u) __nanosleep(64);
        __threadfence();
    }
    __syncthreads();

    // ================= proven streaming segment-sum =================
    const int off = g_off[s];
    const int cnt = g_cnt[s];

    if ((int)blockIdx.x < (int)gridDim.x - 1) {
        int e = blockIdx.x * 256 + tid;
        if (e < n4_bert) {
            const float4* base = (const float4*)bert + (size_t)off * n4_bert + e;
            float4 acc = make_float4(0.f, 0.f, 0.f, 0.f);
            for (int j = 0; j < cnt; j++) {
                float  w = g_w[off + j];
                float4 v = __ldg(base + (size_t)j * n4_bert);
                acc.x = fmaf(w, v.x, acc.x);
                acc.y = fmaf(w, v.y, acc.y);
                acc.z = fmaf(w, v.z, acc.z);
                acc.w = fmaf(w, v.w, acc.w);
            }
            __stcs((float4*)out_bert + (size_t)s * n4_bert + e, acc);
        }
    } else {
        int e = tid;
        if (e < n4_mtl) {
            const float4* base = (const float4*)mtl + (size_t)off * n4_mtl + e;
            float4 acc = make_float4(0.f, 0.f, 0.f, 0.f);
            for (int j = 0; j < cnt; j++) {
                float  w = g_w[off + j];
                float4 v = __ldg(base + (size_t)j * n4_mtl);
                acc.x = fmaf(w, v.x, acc.x);
                acc.y = fmaf(w, v.y, acc.y);
                acc.z = fmaf(w, v.z, acc.z);
                acc.w = fmaf(w, v.w, acc.w);
            }
            ((float4*)out_mtl)[(size_t)s * n4_mtl + e] = acc;
        }
    }

    // ================= reset for next (graph-replayed) launch =================
    __syncthreads();
    if (tid == 0) {
        __threadfence();
        unsigned int d = atomicAdd(&g_done, 1u);
        if (d == total - 1) {
            g_flag = 0u;
            g_ctr  = 0u;
            g_done = 0u;
        }
    }
}

// ---------------------------------------------------------------------------
// Launch. Inputs (metadata order):
//   0: bert_representation (rows, seq, hidden) f32
//   1: history_attention_input (rows, hidden)  f32
//   2: mtl_input (rows, hidden)                f32
//   3: W (1, hidden) f32     4: b (1,) f32
//   5: slice_mask (rows,) i32   6: slice_num i32 (S derived from out_size)
// Output: [new_bert (S,seq,hidden) | new_mtl (S,hidden) | probs (S,T_MAX)] f32
// ---------------------------------------------------------------------------
extern "C" void kernel_launch(void* const* d_in, const int* in_sizes, int n_in,
                              void* d_out, int out_size)
{
    const float* bert = (const float*)d_in[0];
    const float* hist = (const float*)d_in[1];
    const float* mtl  = (const float*)d_in[2];
    const float* Wv   = (const float*)d_in[3];
    const float* bv   = (const float*)d_in[4];
    const int*   sm   = (const int*)d_in[5];

    const int hidden = in_sizes[3];                   // 768
    const int rows   = in_sizes[1] / hidden;          // 64
    const int seq    = in_sizes[0] / (rows * hidden); // 512
    const int S      = out_size / (seq * hidden + hidden + T_MAX); // 16

    float* out_bert  = (float*)d_out;
    float* out_mtl   = out_bert + (size_t)S * seq * hidden;
    float* out_probs = out_mtl  + (size_t)S * hidden;

    const int n4_bert = seq * hidden / 4;   // 98304
    const int n4_mtl  = hidden / 4;         // 192

    dim3 grid((n4_bert + 255) / 256 + 1, S);  // (385, 16)
    k_all<<<grid, 256>>>(bert, hist, mtl, Wv, bv, sm,
                         out_bert, out_mtl, out_probs,
                         rows, hidden, n4_bert, n4_mtl, S);
}

// round 11
// speedup vs baseline: 1.2347x; 1.2347x over previous
#include <cuda_runtime.h>
#include <cuda_bf16.h>

#define T_MAX 11

// Kernel-A -> Kernel-B handoff (graph edge orders the kernels).
__device__ float g_e[1024];

// ---------------------------------------------------------------------------
// Kernel A: one block per row. g_e[r] = exp(dot(hist[r], W) + b).
// One parallel load round + warp/block reduce. No atomics, no fences.
// ---------------------------------------------------------------------------
__global__ void __launch_bounds__(128)
k_dot(const float* __restrict__ hist,
      const float* __restrict__ Wv,
      const float* __restrict__ bv,
      int hidden)
{
    const int tid  = threadIdx.x;
    const int lane = tid & 31;
    const int warp = tid >> 5;
    const int r    = blockIdx.x;

    __shared__ float s_red[4];

    const int nv4 = hidden >> 2;                    // 192 @ hidden=768
    const float4* hr = (const float4*)(hist + (size_t)r * hidden);
    const float4* wv = (const float4*)Wv;
    float acc = 0.f;
    for (int c = tid; c < nv4; c += 128) {          // 2 independent rounds
        float4 h = __ldg(hr + c);
        float4 w = __ldg(wv + c);
        acc = fmaf(h.x, w.x, acc);
        acc = fmaf(h.y, w.y, acc);
        acc = fmaf(h.z, w.z, acc);
        acc = fmaf(h.w, w.w, acc);
    }
    #pragma unroll
    for (int o = 16; o; o >>= 1)
        acc += __shfl_down_sync(0xffffffffu, acc, o);
    if (lane == 0) s_red[warp] = acc;
    __syncthreads();
    if (tid == 0)
        g_e[r] = __expf(s_red[0] + s_red[1] + s_red[2] + s_red[3] + bv[0]);
}

// ---------------------------------------------------------------------------
// Kernel B: proven streaming segment-sum + lightweight softmax prologue.
// Grid (GX, S), 256 threads, <=32 regs. Prologue per block: read slice_mask
// (S ints) + g_e (cnt<=11 floats, L2-hot), softmax into smem (~50B traffic).
//   blockIdx.x <  GX-1 : 256 float4 chunk of new_bert for segment s
//   blockIdx.x == GX-1 : new_mtl row s + probs row s (incl. zero padding)
// ---------------------------------------------------------------------------
__global__ void __launch_bounds__(256, 8)
k_segsum(const float* __restrict__ bert,
         const float* __restrict__ mtl,
         const int*   __restrict__ slice_mask,
         float* __restrict__ out_bert,
         float* __restrict__ out_mtl,
         float* __restrict__ out_probs,
         int n4_bert, int n4_mtl, int S)
{
    __shared__ int   s_mask[64];
    __shared__ float s_e[T_MAX + 5];
    __shared__ float s_w[T_MAX + 5];

    const int tid = threadIdx.x;
    const int s   = blockIdx.y;

    // ---- prologue: segment geometry + softmax weights ----
    if (tid < S) s_mask[tid] = __ldg(slice_mask + tid);
    __syncthreads();

    int off = 0;
    #pragma unroll 4
    for (int t = 0; t < s; t++) off += s_mask[t];
    const int cnt = s_mask[s];

    if (tid < cnt) s_e[tid] = g_e[off + tid];
    __syncthreads();
    if (tid < cnt) {
        float sum = 0.f;
        for (int j = 0; j < cnt; j++) sum += s_e[j];
        s_w[tid] = s_e[tid] * (1.f / sum);
    }
    __syncthreads();

    // ---- proven stream ----
    if ((int)blockIdx.x < (int)gridDim.x - 1) {
        int e = blockIdx.x * 256 + tid;
        if (e >= n4_bert) return;
        const float4* base = (const float4*)bert + (size_t)off * n4_bert + e;
        float4 acc = make_float4(0.f, 0.f, 0.f, 0.f);
        for (int j = 0; j < cnt; j++) {
            float  w = s_w[j];
            float4 v = __ldg(base + (size_t)j * n4_bert);
            acc.x = fmaf(w, v.x, acc.x);
            acc.y = fmaf(w, v.y, acc.y);
            acc.z = fmaf(w, v.z, acc.z);
            acc.w = fmaf(w, v.w, acc.w);
        }
        ((float4*)out_bert)[(size_t)s * n4_bert + e] = acc;
    } else {
        if (tid < n4_mtl) {
            const float4* base = (const float4*)mtl + (size_t)off * n4_mtl + tid;
            float4 acc = make_float4(0.f, 0.f, 0.f, 0.f);
            for (int j = 0; j < cnt; j++) {
                float  w = s_w[j];
                float4 v = __ldg(base + (size_t)j * n4_mtl);
                acc.x = fmaf(w, v.x, acc.x);
                acc.y = fmaf(w, v.y, acc.y);
                acc.z = fmaf(w, v.z, acc.z);
                acc.w = fmaf(w, v.w, acc.w);
            }
            ((float4*)out_mtl)[(size_t)s * n4_mtl + tid] = acc;
        }
        // probs row s (d_out is poisoned: write all T_MAX slots)
        if (tid < T_MAX) {
            int padl = T_MAX - cnt;
            out_probs[s * T_MAX + tid] = (tid >= padl) ? s_w[tid - padl] : 0.f;
        }
    }
}

// ---------------------------------------------------------------------------
// Launch. Inputs (metadata order):
//   0: bert_representation (rows, seq, hidden) f32
//   1: history_attention_input (rows, hidden)  f32
//   2: mtl_input (rows, hidden)                f32
//   3: W (1, hidden) f32     4: b (1,) f32
//   5: slice_mask (rows,) i32   6: slice_num i32 (S derived from out_size)
// Output: [new_bert (S,seq,hidden) | new_mtl (S,hidden) | probs (S,T_MAX)] f32
// ---------------------------------------------------------------------------
extern "C" void kernel_launch(void* const* d_in, const int* in_sizes, int n_in,
                              void* d_out, int out_size)
{
    const float* bert = (const float*)d_in[0];
    const float* hist = (const float*)d_in[1];
    const float* mtl  = (const float*)d_in[2];
    const float* Wv   = (const float*)d_in[3];
    const float* bv   = (const float*)d_in[4];
    const int*   sm   = (const int*)d_in[5];

    const int hidden = in_sizes[3];                   // 768
    const int rows   = in_sizes[1] / hidden;          // 64
    const int seq    = in_sizes[0] / (rows * hidden); // 512
    const int S      = out_size / (seq * hidden + hidden + T_MAX); // 16

    float* out_bert  = (float*)d_out;
    float* out_mtl   = out_bert + (size_t)S * seq * hidden;
    float* out_probs = out_mtl  + (size_t)S * hidden;

    const int n4_bert = seq * hidden / 4;   // 98304
    const int n4_mtl  = hidden / 4;         // 192

    k_dot<<<rows, 128>>>(hist, Wv, bv, hidden);

    dim3 grid((n4_bert + 255) / 256 + 1, S);  // (385, 16)
    k_segsum<<<grid, 256>>>(bert, mtl, sm,
                            out_bert, out_mtl, out_probs,
                            n4_bert, n4_mtl, S);
}